// round 16
// baseline (speedup 1.0000x reference)
#include <cuda_runtime.h>
#include <cuda_bf16.h>
#include <math.h>

#define NROWS 32768
#define NCODE 8192
#define DIM   512

#define BM 128
#define BN 128
#define NCB (NCODE / BN)   // 64 column blocks
#define KS 64
#define KT (DIM / KS)      // 8
#define NSTAGE 3
#define LDA 72          // KS + 8 pad (bf16): 144B row stride -> conflict-free ldmatrix

#define MARGIN 0.02f
#define MAXCAND 32

#define SMEM_BYTES (NSTAGE * (BM + BN) * LDA * 2)   // 110592

// scratch (no allocations allowed)
__device__ float g_x2[NROWS];
__device__ float g_y2[NCODE];
__device__ unsigned int g_colmax[NROWS * NCB];   // fkey of per-(row, col-block) max
__device__ __nv_bfloat16 g_xb[NROWS * DIM];
__device__ __nv_bfloat16 g_eb[NCODE * DIM];

__device__ __forceinline__ unsigned int fkey(float v) {
    unsigned int b = __float_as_uint(v);
    return (b & 0x80000000u) ? ~b : (b | 0x80000000u);
}
__device__ __forceinline__ float fkey_inv(unsigned int k) {
    unsigned int b = (k & 0x80000000u) ? (k & 0x7FFFFFFFu) : ~k;
    return __uint_as_float(b);
}

__device__ __forceinline__ void cp16(void* dst, const void* src) {
    unsigned d = (unsigned)__cvta_generic_to_shared(dst);
    asm volatile("cp.async.cg.shared.global [%0], [%1], 16;" :: "r"(d), "l"(src));
}
#define CP_COMMIT() asm volatile("cp.async.commit_group;")
#define CP_WAIT1()  asm volatile("cp.async.wait_group 1;")
#define CP_WAIT0()  asm volatile("cp.async.wait_group 0;")

// FUSED bf16 convert + strictly sequential scalar fp32 norm (VALIDATED R15):
// double-buffered cp.async staging; the per-row chain is the identical
// __fadd_rn(s, __fmul_rn(v,v)) ascending sequence -> norm BITWISE IDENTICAL.
#define CLD 68
__global__ __launch_bounds__(128)
void conv_norm_all(const float* __restrict__ x, const float* __restrict__ e) {
    __shared__ float sb[2][128][CLD];

    int t = threadIdx.x;
    int blk = blockIdx.x;
    const float* src;
    __nv_bfloat16* dst;
    float* outp;
    int row0;
    if (blk < NROWS / 128) {
        row0 = blk * 128;
        src = x + (size_t)row0 * DIM;
        dst = g_xb + (size_t)row0 * DIM;
        outp = g_x2 + row0;
    } else {
        row0 = (blk - NROWS / 128) * 128;
        src = e + (size_t)row0 * DIM;
        dst = g_eb + (size_t)row0 * DIM;
        outp = g_y2 + row0;
    }

    auto issue = [&](int c, int b) {
        #pragma unroll
        for (int i = 0; i < 16; i++) {
            int id = t + i * 128;
            int r = id >> 4, sg = id & 15;
            cp16(&sb[b][r][sg * 4], src + (size_t)r * DIM + c * 64 + sg * 4);
        }
    };

    issue(0, 0); CP_COMMIT();

    float s = 0.0f;
    #pragma unroll 1
    for (int c = 0; c < 8; c++) {
        int cur = c & 1;
        if (c + 1 < 8) { issue(c + 1, (c + 1) & 1); CP_COMMIT(); CP_WAIT1(); }
        else { CP_WAIT0(); }
        __syncthreads();

        #pragma unroll 8
        for (int k = 0; k < 64; k++) {
            float v = sb[cur][t][k];
            s = __fadd_rn(s, __fmul_rn(v, v));
        }

        #pragma unroll
        for (int i = 0; i < 32; i++) {
            int id = t + i * 128;
            int r = id >> 5, sg = id & 31;
            __nv_bfloat162 pr = __floats2bfloat162_rn(sb[cur][r][sg * 2],
                                                      sb[cur][r][sg * 2 + 1]);
            *reinterpret_cast<__nv_bfloat162*>(
                dst + (size_t)r * DIM + c * 64 + sg * 2) = pr;
        }
        __syncthreads();
    }
    outp[t] = s;
}

__device__ __forceinline__ void ldsm_x4(unsigned& r0, unsigned& r1, unsigned& r2, unsigned& r3,
                                        const void* ptr) {
    unsigned addr = (unsigned)__cvta_generic_to_shared(ptr);
    asm volatile("ldmatrix.sync.aligned.m8n8.x4.shared.b16 {%0,%1,%2,%3}, [%4];"
                 : "=r"(r0), "=r"(r1), "=r"(r2), "=r"(r3) : "r"(addr));
}
__device__ __forceinline__ void mma_bf16(float* c, const unsigned* a, const unsigned* b) {
    asm volatile(
        "mma.sync.aligned.m16n8k16.row.col.f32.bf16.bf16.f32 "
        "{%0,%1,%2,%3}, {%4,%5,%6,%7}, {%8,%9}, {%0,%1,%2,%3};"
        : "+f"(c[0]), "+f"(c[1]), "+f"(c[2]), "+f"(c[3])
        : "r"(a[0]), "r"(a[1]), "r"(a[2]), "r"(a[3]), "r"(b[0]), "r"(b[1]));
}

// fast sqrt on the FMA pipe (no MUFU): rsqrt bit-hack + 2 Newton, ~4e-6 rel.
__device__ __forceinline__ float negdist(float x2, float y2, float sxy) {
    float dsq = __fadd_rn(__fadd_rn(x2, y2), __fmul_rn(-2.0f, sxy));
    dsq = fmaxf(dsq, 1e-12f);
    float r = __uint_as_float(0x5f37642fu - (__float_as_uint(dsq) >> 1));
    r = r * fmaf(-0.5f * dsq * r, r, 1.5f);
    r = r * fmaf(-0.5f * dsq * r, r, 1.5f);
    return -(dsq * r);
}

// bf16 tensor-core GEMM: 4 warps, warp tile 64x64 (2x2 warp grid).
// LDSM redundancy drops from 6 to 4 tile-reads per kt -> smem crossbar
// (the R9-R15 co-bottleneck) goes below the tensor-pipe demand.
__global__ __launch_bounds__(128)
void gemm_bf16(float* __restrict__ dist) {
    extern __shared__ __nv_bfloat16 smem[];
    __nv_bfloat16* As = smem;                            // [NSTAGE][BM][LDA]
    __nv_bfloat16* Bs = smem + NSTAGE * BM * LDA;        // [NSTAGE][BN][LDA]

    int tid = threadIdx.x;
    int wid = tid >> 5, lane = tid & 31;
    int warp_m = wid >> 1, warp_n = wid & 1;             // 2 x 2 warps, warp tile 64x64
    int bm = blockIdx.y * BM, bn = blockIdx.x * BN;

    const __nv_bfloat16* xg = g_xb + (size_t)bm * DIM;
    const __nv_bfloat16* eg = g_eb + (size_t)bn * DIM;

    float acc[4][8][4] = {};

    // loader: 128 threads, per kt A+B = 2048 16B granules -> 16 cp16/thread
    auto issue = [&](int kt, int s) {
        const __nv_bfloat16* xsrc = xg + kt * KS;
        const __nv_bfloat16* esrc = eg + kt * KS;
        __nv_bfloat16* Ad = As + (size_t)s * BM * LDA;
        __nv_bfloat16* Bd = Bs + (size_t)s * BN * LDA;
        #pragma unroll
        for (int i = 0; i < 8; i++) {
            int id = tid + i * 128;
            int row = id >> 3, seg = id & 7;
            cp16(Ad + row * LDA + seg * 8, xsrc + (size_t)row * DIM + seg * 8);
            cp16(Bd + row * LDA + seg * 8, esrc + (size_t)row * DIM + seg * 8);
        }
    };

    issue(0, 0); CP_COMMIT();
    issue(1, 1); CP_COMMIT();

    int sc = 0, si = 2;
    #pragma unroll 1
    for (int kt = 0; kt < KT; kt++) {
        CP_WAIT1();
        __syncthreads();
        if (kt + NSTAGE - 1 < KT) issue(kt + NSTAGE - 1, si);
        CP_COMMIT();

        const __nv_bfloat16* Ab = As + (size_t)sc * BM * LDA;
        const __nv_bfloat16* Bb = Bs + (size_t)sc * BN * LDA;
        #pragma unroll
        for (int kk = 0; kk < 4; kk++) {
            unsigned a[4][4], b[8][2];
            #pragma unroll
            for (int mi = 0; mi < 4; mi++)
                ldsm_x4(a[mi][0], a[mi][1], a[mi][2], a[mi][3],
                        Ab + (warp_m * 64 + mi * 16 + (lane & 15)) * LDA
                           + kk * 16 + ((lane >> 4) << 3));
            #pragma unroll
            for (int nib = 0; nib < 4; nib++) {
                unsigned r0, r1, r2, r3;
                ldsm_x4(r0, r1, r2, r3,
                        Bb + (warp_n * 64 + nib * 16 + ((lane >> 4) << 3) + (lane & 7)) * LDA
                           + kk * 16 + (((lane >> 3) & 1) << 3));
                b[nib * 2][0] = r0; b[nib * 2][1] = r1;
                b[nib * 2 + 1][0] = r2; b[nib * 2 + 1][1] = r3;
            }
            #pragma unroll
            for (int mi = 0; mi < 4; mi++)
                #pragma unroll
                for (int ni = 0; ni < 8; ni++)
                    mma_bf16(acc[mi][ni], a[mi], b[ni]);
        }
        sc = (sc + 1 == NSTAGE) ? 0 : sc + 1;
        si = (si + 1 == NSTAGE) ? 0 : si + 1;
    }

    // epilogue: dist (streaming stores) + per-(row, col-block) max via smem
    int qr = lane >> 2, qc = 2 * (lane & 3);
    float x2v[4][2], rmax[4][2];
    #pragma unroll
    for (int mi = 0; mi < 4; mi++)
        #pragma unroll
        for (int h = 0; h < 2; h++) {
            x2v[mi][h] = g_x2[bm + warp_m * 64 + mi * 16 + h * 8 + qr];
            rmax[mi][h] = -1e30f;
        }

    #pragma unroll
    for (int ni = 0; ni < 8; ni++) {
        int n0 = bn + warp_n * 64 + ni * 8 + qc;
        float y0 = g_y2[n0], y1 = g_y2[n0 + 1];
        #pragma unroll
        for (int mi = 0; mi < 4; mi++)
            #pragma unroll
            for (int h = 0; h < 2; h++) {
                int rg = bm + warp_m * 64 + mi * 16 + h * 8 + qr;
                float d0 = negdist(x2v[mi][h], y0, acc[mi][ni][2 * h]);
                float d1 = negdist(x2v[mi][h], y1, acc[mi][ni][2 * h + 1]);
                __stcs(reinterpret_cast<float2*>(&dist[(size_t)rg * NCODE + n0]),
                       make_float2(d0, d1));
                rmax[mi][h] = fmaxf(rmax[mi][h], fmaxf(d0, d1));
            }
    }

    // smem reduction across the 2 warp_n warps (no atomics, no init kernel)
    float* s_rm = reinterpret_cast<float*>(smem);    // [2][BM] = 1KB
    __syncthreads();
    #pragma unroll
    for (int mi = 0; mi < 4; mi++)
        #pragma unroll
        for (int h = 0; h < 2; h++) {
            float v = rmax[mi][h];
            v = fmaxf(v, __shfl_xor_sync(0xffffffffu, v, 1));
            v = fmaxf(v, __shfl_xor_sync(0xffffffffu, v, 2));
            if ((lane & 3) == 0)
                s_rm[warp_n * BM + warp_m * 64 + mi * 16 + h * 8 + qr] = v;
        }
    __syncthreads();
    if (tid < BM) {
        float v = fmaxf(s_rm[tid], s_rm[BM + tid]);
        g_colmax[(size_t)(bm + tid) * NCB + blockIdx.x] = fkey(v);
    }
}

// one warp per row: approx row max from the 64 block maxima, scan ONLY
// qualifying blocks, re-evaluate with the EXACT validated chain, write out_ind,
// gather embed row into out_q (finalize fused).
#define RWARPS 8
__global__ __launch_bounds__(256)
void rescue(const float* __restrict__ x, const float* __restrict__ e,
            const float* __restrict__ dist,
            float* __restrict__ out_q, float* __restrict__ out_ind) {
    __shared__ int s_cnt[RWARPS];
    __shared__ int s_cand[RWARPS][MAXCAND];

    int w = threadIdx.x >> 5, lane = threadIdx.x & 31;
    int row = blockIdx.x * RWARPS + w;

    if (lane == 0) s_cnt[w] = 0;
    __syncwarp();

    float cm0 = fkey_inv(g_colmax[(size_t)row * NCB + lane]);
    float cm1 = fkey_inv(g_colmax[(size_t)row * NCB + 32 + lane]);
    float m = fmaxf(cm0, cm1);
    #pragma unroll
    for (int off = 16; off > 0; off >>= 1)
        m = fmaxf(m, __shfl_xor_sync(0xffffffffu, m, off));
    float thr = m - MARGIN;

    const float* dp = dist + (size_t)row * NCODE;
    #pragma unroll 1
    for (int b = 0; b < NCB; b++) {
        float cb = (b < 32) ? __shfl_sync(0xffffffffu, cm0, b)
                            : __shfl_sync(0xffffffffu, cm1, b - 32);
        if (cb >= thr) {
            float4 v = *reinterpret_cast<const float4*>(dp + b * BN + lane * 4);
            #pragma unroll
            for (int q = 0; q < 4; q++) {
                float dv = (q == 0) ? v.x : (q == 1) ? v.y : (q == 2) ? v.z : v.w;
                if (dv >= thr) {
                    int slot = atomicAdd(&s_cnt[w], 1);
                    if (slot < MAXCAND) s_cand[w][slot] = b * BN + lane * 4 + q;
                }
            }
        }
    }
    __syncwarp();
    int cnt = s_cnt[w];
    if (cnt > MAXCAND) cnt = MAXCAND;

    int best;
    if (cnt == 1) {
        best = s_cand[w][0];       // single candidate IS the argmax
    } else {
        unsigned long long key = 0ull;
        if (lane < cnt) {
            int c = s_cand[w][lane];
            const float* xr = x + (size_t)row * DIM;
            const float* er = e + (size_t)c * DIM;
            // EXACT validated chain: strictly ascending-k fp32 FMA sequence
            float s = 0.0f;
            #pragma unroll 4
            for (int k = 0; k < DIM; k += 4) {
                float4 xa = *reinterpret_cast<const float4*>(xr + k);
                float4 ea = *reinterpret_cast<const float4*>(er + k);
                s = fmaf(xa.x, ea.x, s);
                s = fmaf(xa.y, ea.y, s);
                s = fmaf(xa.z, ea.z, s);
                s = fmaf(xa.w, ea.w, s);
            }
            float xyv = __fmul_rn(-2.0f, s);
            float t   = __fadd_rn(g_x2[row], g_y2[c]);
            float dsq = __fadd_rn(t, xyv);
            float dv  = -sqrtf(fmaxf(dsq, 0.0f));
            key = ((unsigned long long)fkey(dv) << 32) | (unsigned int)(NCODE - 1 - c);
        }
        #pragma unroll
        for (int off = 16; off > 0; off >>= 1) {
            unsigned long long o = __shfl_xor_sync(0xffffffffu, key, off);
            key = (o > key) ? o : key;
        }
        best = (NCODE - 1) - (int)(unsigned int)(__shfl_sync(0xffffffffu, key, 0) & 0xFFFFFFFFull);
    }

    if (lane == 0) out_ind[row] = (float)best;
    const float4* src = reinterpret_cast<const float4*>(e + (size_t)best * DIM);
    float4* dst = reinterpret_cast<float4*>(out_q + (size_t)row * DIM);
    #pragma unroll
    for (int j = 0; j < DIM / 4 / 32; j++)
        __stcs(&dst[lane + 32 * j], src[lane + 32 * j]);
}

extern "C" void kernel_launch(void* const* d_in, const int* in_sizes, int n_in,
                              void* d_out, int out_size) {
    const float* x = (const float*)d_in[0];      // [32768, 512]
    const float* e = (const float*)d_in[1];      // [8192, 512]
    float* out = (float*)d_out;

    float* out_q    = out;                                   // [N, D]
    float* out_ind  = out + (size_t)NROWS * DIM;             // [N]
    float* out_dist = out + (size_t)NROWS * DIM + NROWS;     // [N, C]

    cudaFuncSetAttribute(gemm_bf16, cudaFuncAttributeMaxDynamicSharedMemorySize, SMEM_BYTES);

    conv_norm_all<<<(NROWS + NCODE) / 128, 128>>>(x, e);

    dim3 grid(NCODE / BN, NROWS / BM);
    gemm_bf16<<<grid, 128, SMEM_BYTES>>>(out_dist);

    rescue<<<NROWS / RWARPS, 256>>>(x, e, out_dist, out_q, out_ind);
}